// round 4
// baseline (speedup 1.0000x reference)
#include <cuda_runtime.h>
#include <string.h>

// ---------------------------------------------------------------------------
// GraphFeatureTokenizer fused kernel for GB300 (sm_103a) — Round 4
//
// R3 was issue/latency bound: pack-MOVs 1:1 with FFMA2, weight slice re-read
// from smem every 8 tokens (L1 68.6%), occ 33.5%.
// R4: token-pair packed GEMM. ie stored TRANSPOSED in smem so the packed
// (x_m, x_m+1) operand is a direct broadcast LDS.128 (no MOVs); only the
// weight is duplicated, reused across 8 token-pairs (MOV:FFMA2 = 1:4).
// TM=16 tokens/tile with 2 cols/thread (GSZ=128) quarters weight-smem
// traffic. TPB=512 with 2 CTAs/SM -> 32 warps/SM.
// ---------------------------------------------------------------------------

#define HID      768
#define HID2     384              // float2 per row
#define NSPLIT   3
#define SCOLS2   128              // float2 cols per split
#define MAXLEN   15360
#define NB       8
#define SLOTS    (NB * MAXLEN)    // 122880
#define TM       16
#define MP       8                // token pairs per tile
#define NTILES   (SLOTS / TM)     // 7680
#define TPB      512
#define NGRP     4
#define GSZ      128
#define NWORK    101

#define F_ELEMS  (SLOTS * HID)    // 94371840
#define M_ELEMS  (SLOTS)          // 122880
#define I_ELEMS  (SLOTS * 2)      // 245760

#define IETPAD   20               // floats per k-row of transposed ie (80B, 16B-aligned)
#define SM_W_BYTES    65536                       // 64 x 256 f32 slice
#define SM_IET_BYTES  (NGRP * 64 * IETPAD * 4)    // 20480
#define SM_META_INTS  (NGRP * TM * 5)             // 320
#define SM_OFF_INTS   32
#define SMEM_BYTES    (SM_W_BYTES + SM_IET_BYTES + (SM_META_INTS + SM_OFF_INTS) * 4)

typedef unsigned long long ull;

__device__ __forceinline__ ull pack2(float x) {
    float2 q = make_float2(x, x);
    ull r; memcpy(&r, &q, 8);
    return r;
}
__device__ __forceinline__ float2 unpack2(ull v) {
    float2 r; memcpy(&r, &v, 8);
    return r;
}
__device__ __forceinline__ void fma2(ull& acc, ull a, ull b) {
    asm("fma.rn.f32x2 %0, %1, %2, %0;" : "+l"(acc) : "l"(a), "l"(b));
}
__device__ __forceinline__ void pf_l2(const void* p) {
    asm volatile("prefetch.global.L2 [%0];" :: "l"(p));
}

extern "C" __global__ void __launch_bounds__(TPB, 2)
gft_kernel(const float* __restrict__ embedW,
           const float* __restrict__ lapW,
           const float* __restrict__ orderW,
           const float* __restrict__ eig,
           const int*   __restrict__ nodeData,
           const int*   __restrict__ edgeData,
           const int*   __restrict__ edgeIndex,
           const int*   __restrict__ nodeNum,
           const int*   __restrict__ edgeNum,
           float*       __restrict__ out,
           int Etot, int extraMode)
{
    extern __shared__ float smem[];
    float2* sW2   = (float2*)smem;                        // [64 k][128 c2]
    float*  sIET  = smem + SM_W_BYTES / 4;                // [NGRP][64 k][IETPAD]
    int*    sMeta = (int*)(sIET + SM_IET_BYTES / 4);      // [NGRP][TM][5]
    int*    sOff  = sMeta + SM_META_INTS;                 // [32]

    const int tid    = threadIdx.x;
    const int nwork  = gridDim.x / NSPLIT;
    const int split  = blockIdx.x / nwork;                // 0..2
    const int worker = blockIdx.x - split * nwork;

    // --- init: weight slice -> smem as float2, prefix sums ---
    {
        const float2* s = (const float2*)lapW;
        #pragma unroll 4
        for (int i = tid; i < 64 * SCOLS2; i += TPB) {
            const int k = i >> 7, c2 = i & 127;
            sW2[i] = s[k * HID2 + split * SCOLS2 + c2];
        }
    }
    if (tid < NB) {
        int no = 0, eo = 0;
        for (int x = 0; x < tid; x++) { no += nodeNum[x]; eo += edgeNum[x]; }
        sOff[tid]      = no;
        sOff[8 + tid]  = eo;
        sOff[16 + tid] = nodeNum[tid];
        sOff[24 + tid] = nodeNum[tid] + edgeNum[tid];
    }
    __syncthreads();

    const int g  = tid >> 7;                 // group 0..3 (128 threads each)
    const int lt = tid & 127;
    float* gIET  = sIET + g * 64 * IETPAD;
    int*   gMeta = sMeta + g * TM * 5;
    const int barid = 1 + g;
    const int grp   = worker * NGRP + g;
    const int ngrp  = nwork * NGRP;
    const int cb2   = split * SCOLS2 + lt;   // this thread's float2 col

    for (int tile = grp; tile < NTILES; tile += ngrp) {
        const int slot0 = tile * TM;
        const int b  = slot0 / MAXLEN;
        const int t0 = slot0 - b * MAXLEN;
        const int nOff = sOff[b], eOff = sOff[8 + b];
        const int nn = sOff[16 + b], seq = sOff[24 + b];

        if (t0 >= seq) {
            if (split == 0 && lt < TM && extraMode) {
                const int slot = slot0 + lt;
                if (extraMode == 1) {
                    out[(size_t)F_ELEMS + slot] = 1.0f;
                    out[(size_t)F_ELEMS + M_ELEMS + 2 * slot]     = 0.0f;
                    out[(size_t)F_ELEMS + M_ELEMS + 2 * slot + 1] = 0.0f;
                } else {
                    ((unsigned char*)out)[(size_t)F_ELEMS * 4 + slot] = 1;
                    int* ip = (int*)((char*)out + (size_t)F_ELEMS * 4 + M_ELEMS);
                    ip[2 * slot] = 0; ip[2 * slot + 1] = 0;
                }
            }
            const float2 z = make_float2(0.f, 0.f);
            #pragma unroll
            for (int m = 0; m < TM; m++)
                __stcs((float2*)out + (size_t)(slot0 + m) * HID2 + cb2, z);
            continue;
        }

        // --- phase A: metadata (lanes 0..15), L2 prefetch, transposed ie ---
        if (lt < TM) {
            const int m = lt, t = t0 + m;
            int r0 = 0, r1 = 0, r2 = 0, r3 = 0, ord = 1, i0 = 0, i1 = 0;
            const bool pad = (t >= seq);
            if (!pad) {
                if (t < nn) {
                    int4 rr = ((const int4*)nodeData)[nOff + t];
                    r0 = rr.x; r1 = rr.y; r2 = rr.z; r3 = rr.w;
                    i0 = t; i1 = t; ord = 1;
                } else {
                    const int ge = eOff + (t - nn);
                    int4 rr = ((const int4*)edgeData)[ge];
                    r0 = rr.x; r1 = rr.y; r2 = rr.z; r3 = rr.w;
                    i0 = edgeIndex[ge]; i1 = edgeIndex[Etot + ge];
                    ord = (i0 == i1) ? 1 : 0;
                }
            }
            gMeta[m * 5 + 0] = r0; gMeta[m * 5 + 1] = r1;
            gMeta[m * 5 + 2] = r2; gMeta[m * 5 + 3] = r3;
            gMeta[m * 5 + 4] = ord;
            if (split == 0 && extraMode) {
                const int slot = slot0 + m;
                if (extraMode == 1) {
                    out[(size_t)F_ELEMS + slot] = pad ? 1.0f : 0.0f;
                    out[(size_t)F_ELEMS + M_ELEMS + 2 * slot]     = (float)i0;
                    out[(size_t)F_ELEMS + M_ELEMS + 2 * slot + 1] = (float)i1;
                } else {
                    ((unsigned char*)out)[(size_t)F_ELEMS * 4 + slot] = pad ? 1 : 0;
                    int* ip = (int*)((char*)out + (size_t)F_ELEMS * 4 + M_ELEMS);
                    ip[2 * slot] = i0; ip[2 * slot + 1] = i1;
                }
            }
        }
        {
            // L2 prefetch: thread (m = lt>>3, j = lt&7): line j of token m's
            // 4 embed rows, restricted to this split's 1KB slice.
            const int m = lt >> 3, j = lt & 7;
            const int t = t0 + m;
            if (t < seq) {
                int4 rr;
                if (t < nn) rr = ((const int4*)nodeData)[nOff + t];
                else        rr = ((const int4*)edgeData)[eOff + (t - nn)];
                const char* eb = (const char*)embedW + (size_t)split * 1024 + j * 128;
                pf_l2(eb + (size_t)rr.x * 3072);
                pf_l2(eb + (size_t)rr.y * 3072);
                pf_l2(eb + (size_t)rr.z * 3072);
                pf_l2(eb + (size_t)rr.w * 3072);
            }
        }
        {
            // transposed ie: thread (m = lt>>3, kc = (lt&7)*8) loads 8 k-values
            // of token m and scatters them to ieT[k][m].
            const int m = lt >> 3;
            const int kc = (lt & 7) * 8;
            const int t = t0 + m;
            const bool pad = (t >= seq);
            int row = 0;
            if (!pad) {
                if (t < nn) row = nOff + t;
                else {
                    const int ge = eOff + (t - nn);
                    row = nOff + ((kc < 32) ? edgeIndex[ge] : edgeIndex[Etot + ge]);
                }
            }
            const int jj = kc & 31;
            const float4* er4 = (const float4*)(eig + (size_t)row * 32 + jj);
            float4 v0, v1;
            if (pad) { v0 = make_float4(0,0,0,0); v1 = v0; }
            else     { v0 = er4[0]; v1 = er4[1]; }
            float* dst = gIET + kc * IETPAD + m;
            dst[0 * IETPAD] = v0.x; dst[1 * IETPAD] = v0.y;
            dst[2 * IETPAD] = v0.z; dst[3 * IETPAD] = v0.w;
            dst[4 * IETPAD] = v1.x; dst[5 * IETPAD] = v1.y;
            dst[6 * IETPAD] = v1.z; dst[7 * IETPAD] = v1.w;
        }
        asm volatile("bar.sync %0, %1;" :: "r"(barid), "r"(GSZ) : "memory");

        // --- phase B: GEMM ie[16][64] @ Wslice[64][256], token-pair packed ---
        ull acc[MP][2];
        #pragma unroll
        for (int mp = 0; mp < MP; mp++) { acc[mp][0] = 0ull; acc[mp][1] = 0ull; }

        #pragma unroll 2
        for (int kq = 0; kq < 16; kq++) {
            // duplicate weight pairs for 4 k-rows x this thread's 2 cols
            ull wd0[4], wd1[4];
            #pragma unroll
            for (int r = 0; r < 4; r++) {
                const float2 w = sW2[(4 * kq + r) * SCOLS2 + lt];
                wd0[r] = pack2(w.x);
                wd1[r] = pack2(w.y);
            }
            #pragma unroll
            for (int r = 0; r < 4; r++) {
                const ull* xr = (const ull*)(gIET + (4 * kq + r) * IETPAD);
                #pragma unroll
                for (int q = 0; q < 4; q++) {
                    // broadcast LDS.128: token pairs (2q, 2q+1) for this k
                    ulonglong2 xp = ((const ulonglong2*)xr)[q];
                    fma2(acc[2 * q    ][0], xp.x, wd0[r]);
                    fma2(acc[2 * q    ][1], xp.x, wd1[r]);
                    fma2(acc[2 * q + 1][0], xp.y, wd0[r]);
                    fma2(acc[2 * q + 1][1], xp.y, wd1[r]);
                }
            }
        }

        // --- phase C: embed gather (L2-hot) + order + store ---
        const float2* em2 = (const float2*)embedW;
        const float2* ow2 = (const float2*)orderW;
        #pragma unroll
        for (int m = 0; m < TM; m++) {
            const int t = t0 + m;
            float2* o2 = (float2*)out + (size_t)(slot0 + m) * HID2 + cb2;
            if (t >= seq) {
                __stcs(o2, make_float2(0.f, 0.f));
            } else {
                const int r0 = gMeta[m * 5 + 0], r1 = gMeta[m * 5 + 1];
                const int r2 = gMeta[m * 5 + 2], r3 = gMeta[m * 5 + 3];
                const int ord = gMeta[m * 5 + 4];
                const float2 e0 = em2[(size_t)r0 * HID2 + cb2];
                const float2 e1 = em2[(size_t)r1 * HID2 + cb2];
                const float2 e2 = em2[(size_t)r2 * HID2 + cb2];
                const float2 e3 = em2[(size_t)r3 * HID2 + cb2];
                const float2 w  = ow2[(size_t)ord * HID2 + cb2];
                const float2 a0 = unpack2(acc[m >> 1][0]);   // col 2*cb2
                const float2 a1 = unpack2(acc[m >> 1][1]);   // col 2*cb2+1
                float2 v;
                if (m & 1) { v.x = a0.y; v.y = a1.y; }
                else       { v.x = a0.x; v.y = a1.x; }
                v.x += e0.x + e1.x + e2.x + e3.x + w.x;
                v.y += e0.y + e1.y + e2.y + e3.y + w.y;
                __stcs(o2, v);
            }
        }
        asm volatile("bar.sync %0, %1;" :: "r"(barid), "r"(GSZ) : "memory");
    }
}

extern "C" void kernel_launch(void* const* d_in, const int* in_sizes, int n_in,
                              void* d_out, int out_size)
{
    const float* embedW   = (const float*)d_in[0];
    const float* lapW     = (const float*)d_in[1];
    const float* orderW   = (const float*)d_in[2];
    const float* eig      = (const float*)d_in[3];
    const int*   nodeData = (const int*)d_in[4];
    const int*   edgeData = (const int*)d_in[5];
    const int*   edgeIdx  = (const int*)d_in[6];
    const int*   nodeNum  = (const int*)d_in[7];
    const int*   edgeNum  = (const int*)d_in[8];

    const int Etot = in_sizes[6] / 2;

    int extraMode = 0;
    const long long allF  = (long long)F_ELEMS + M_ELEMS + I_ELEMS;           // 94740480
    const long long rawB  = (long long)F_ELEMS + (M_ELEMS + I_ELEMS * 4) / 4; // 94648320
    if ((long long)out_size == allF)      extraMode = 1;
    else if ((long long)out_size == rawB) extraMode = 2;

    cudaFuncSetAttribute(gft_kernel, cudaFuncAttributeMaxDynamicSharedMemorySize, SMEM_BYTES);
    gft_kernel<<<NWORK * NSPLIT, TPB, SMEM_BYTES>>>(embedW, lapW, orderW, eig,
                                                    nodeData, edgeData, edgeIdx,
                                                    nodeNum, edgeNum,
                                                    (float*)d_out, Etot, extraMode);
}